// round 6
// baseline (speedup 1.0000x reference)
#include <cuda_runtime.h>
#include <cstddef>
#include <cstdint>

#define BB       32
#define LL       32768
#define CC       128
#define C2       64          // channel pairs (float2)
#define KK       64
#define PADL     31          // SAME, K even: pad_low = 31, out[t] = sum_k x[t+k-31]*w[k]

#define NTHREADS 512
#define TL       128         // rows per tile
#define NT       8           // tiles per strip
#define STRIP    (TL * NT)   // 1024 rows
#define NSTRIPS  (LL / STRIP)// 32
#define TSUB     8
#define TT       (TL / TSUB) // 16 outputs per thread

#define SLOT_ROWS 128
#define NSLOTS    3
#define SMEM_X_F  (NSLOTS * SLOT_ROWS * CC)        // 49152 floats = 192 KB
#define SMEM_W_F  (KK * CC)                        // 8192 floats  = 32 KB
#define SMEM_BYTES ((SMEM_X_F + SMEM_W_F) * 4)     // 229376 B

typedef unsigned long long ull;

// Blackwell packed dual-FMA (FFMA2 in SASS): 2x fp32 FMA per issue.
__device__ __forceinline__ ull ffma2(ull a, ull b, ull c) {
    ull d;
    asm("fma.rn.f32x2 %0, %1, %2, %3;" : "=l"(d) : "l"(a), "l"(b), "l"(c));
    return d;
}

// Accurate cheap tanh: exp form + Taylor branch near 0. Error ~1e-6.
__device__ __forceinline__ float fast_tanh(float x) {
    float xc = fminf(fmaxf(x, -15.0f), 15.0f);
    float t  = __expf(2.0f * xc);
    float r  = __fdividef(t - 1.0f, t + 1.0f);
    float x2 = x * x;
    float p  = x * (1.0f + x2 * (-0.33333334f + 0.13333334f * x2));
    return (fabsf(x) < 0.05f) ? p : r;
}

// ---- cp.async helpers (LDGSTS) ----
__device__ __forceinline__ void cp_async16(uint32_t saddr, const void* gptr, bool pred) {
    int sz = pred ? 16 : 0;   // src-size 0 -> zero-fill destination (OOB rows)
    asm volatile("cp.async.cg.shared.global [%0], [%1], 16, %2;\n"
                 :: "r"(saddr), "l"(gptr), "r"(sz));
}
__device__ __forceinline__ void cp_commit() {
    asm volatile("cp.async.commit_group;\n");
}
__device__ __forceinline__ void cp_wait1() {
    asm volatile("cp.async.wait_group 1;\n");
}

// Prefetch one 128-row block (rel rows [blk*128, blk*128+128)) into a slot.
__device__ __forceinline__ void load_block(float* sx, int slot, int blk,
                                           const float* xb, int base_t, int tid) {
    uint32_t sbase = (uint32_t)__cvta_generic_to_shared(sx + slot * SLOT_ROWS * CC);
    #pragma unroll
    for (int n = 0; n < (SLOT_ROWS * CC / 4) / NTHREADS; n++) {   // 8 iters
        int idx = tid + n * NTHREADS;        // 0..4095 float4 slots
        int r   = idx >> 5;                  // row in block (CC/4 = 32 f4/row)
        int col = idx & 31;
        int g   = base_t + blk * SLOT_ROWS + r;
        bool ok = ((unsigned)g < (unsigned)LL);
        int gs  = ok ? g : 0;                // keep src address sane when masked
        const void* src = xb + (size_t)gs * CC + col * 4;
        cp_async16(sbase + (uint32_t)(r * CC + col * 4) * 4, src, ok);
    }
}

__global__ __launch_bounds__(NTHREADS, 1)
void dwconv1d_tanh_strip_kernel(const float* __restrict__ x,
                                const float* __restrict__ w,     // [K][C]
                                const float* __restrict__ bias,  // [C]
                                float* __restrict__ out) {
    extern __shared__ float sm[];
    float* sx = sm;                   // NSLOTS x [128][CC]
    float* sw = sm + SMEM_X_F;        // [KK][CC]

    const int tid   = threadIdx.x;
    const int blkid = blockIdx.x;
    const int b     = blkid >> 5;     // NSTRIPS = 32
    const int strip = blkid & 31;
    const int t0    = strip * STRIP;
    const int base_t = t0 - 32;       // rel row r <-> global time base_t + r
    const float* xb = x + (size_t)b * LL * CC;

    // ---- group 0: weights + blocks 0,1 ----
    {
        uint32_t wb = (uint32_t)__cvta_generic_to_shared(sw);
        #pragma unroll
        for (int n = 0; n < (SMEM_W_F / 4) / NTHREADS; n++) {     // 4 iters
            int idx = tid + n * NTHREADS;
            cp_async16(wb + (uint32_t)idx * 16, w + idx * 4, true);
        }
        load_block(sx, 0, 0, xb, base_t, tid);
        load_block(sx, 1, 1, xb, base_t, tid);
        cp_commit();
    }

    const int c2    = tid & (C2 - 1);
    const int ts    = tid >> 6;       // 0..7 (warp-uniform)
    const int jbase = ts * TT;

    const ull* sw2 = ((const ull*)sw) + c2;
    const float2 bv = ((const float2*)bias)[c2];
    float2* outp = (float2*)out;

    int slotA = 0;                    // slot holding block i
    for (int i = 0; i < NT; i++) {
        __syncthreads();              // everyone done reading tile i-1's slots

        // prefetch block i+2 into slot (i+2)%3 (== slot tile i-1 vacated)
        int slotC = slotA + 2; if (slotC >= NSLOTS) slotC -= NSLOTS;
        if (i + 2 <= NT) load_block(sx, slotC, i + 2, xb, base_t, tid);
        cp_commit();                  // empty group at i == NT-1: fine
        cp_wait1();                   // block i+1 complete (only i+2 may pend)
        __syncthreads();              // make it visible to all threads

        int slotB = slotA + 1; if (slotB >= NSLOTS) slotB -= NSLOTS;
        const ull* pA = ((const ull*)(sx + slotA * SLOT_ROWS * CC)) + c2;
        const ull* pB = ((const ull*)(sx + slotB * SLOT_ROWS * CC)) + c2;

        // row r (relative to block i): r = jbase + 1 + k + j, r in [1,191].
        // r<128 -> slotA row r; else slotB row r-128. (k=63 dead prefetch hits
        // r<=192 -> slotB row <=64: in-bounds, value unused.)
        ull acc[TT];
        #pragma unroll
        for (int j = 0; j < TT; j++) acc[j] = 0ull;

        ull xw[TT];
        #pragma unroll
        for (int q = 0; q < TT; q++) {
            int r = jbase + 1 + q;
            const ull* p = (r < SLOT_ROWS) ? (pA + r * C2) : (pB + (r - SLOT_ROWS) * C2);
            xw[q] = *p;
        }
        ull wk = sw2[0];
        #pragma unroll
        for (int k = 0; k < KK; k++) {
            ull wnext = sw2[((k + 1) & (KK - 1)) * C2];
            int r = jbase + 1 + TT + k;
            const ull* p = (r < SLOT_ROWS) ? (pA + r * C2) : (pB + (r - SLOT_ROWS) * C2);
            ull xnew = *p;

            #pragma unroll
            for (int j = 0; j < TT; j++)
                acc[j] = ffma2(xw[(k + j) & (TT - 1)], wk, acc[j]);

            xw[k & (TT - 1)] = xnew;
            wk = wnext;
        }

        // ---- bias + tanh + store ----
        const size_t ob = ((size_t)b * LL + t0 + i * TL + jbase) * C2 + c2;
        #pragma unroll
        for (int j = 0; j < TT; j++) {
            float2 a = *(float2*)&acc[j];
            float y0 = fast_tanh(a.x + bv.x);
            float y1 = fast_tanh(a.y + bv.y);
            outp[ob + (size_t)j * C2] = make_float2(y0, y1);
        }

        slotA++; if (slotA >= NSLOTS) slotA = 0;
    }
}

extern "C" void kernel_launch(void* const* d_in, const int* in_sizes, int n_in,
                              void* d_out, int out_size) {
    const float* x    = (const float*)d_in[0];
    const float* w    = (const float*)d_in[1];
    const float* bias = (const float*)d_in[2];
    float*       out  = (float*)d_out;

    cudaFuncSetAttribute(dwconv1d_tanh_strip_kernel,
                         cudaFuncAttributeMaxDynamicSharedMemorySize, SMEM_BYTES);

    dwconv1d_tanh_strip_kernel<<<BB * NSTRIPS, NTHREADS, SMEM_BYTES>>>(x, w, bias, out);
}

// round 7
// speedup vs baseline: 1.0735x; 1.0735x over previous
#include <cuda_runtime.h>
#include <cstddef>

#define BB       32
#define LL       32768
#define CC       128
#define KK       64
#define PADL     31          // SAME, K even: out[t] = sum_k x[t+k-31] * w[k]

#define CH       64          // channels per CTA (half of CC)
#define CP       32          // channel pairs per CTA
#define TL       64          // output rows per CTA
#define ROWS     128         // x rows staged: [t0-31, t0+96]
#define NTHREADS 256
#define TSUB     8
#define TT       (TL / TSUB) // 8 outputs per thread

#define SMEM_X_F (ROWS * CH)              // 8192 floats = 32 KB
#define SMEM_W_F (KK * CH)                // 4096 floats = 16 KB
#define SMEM_BYTES ((SMEM_X_F + SMEM_W_F) * 4)   // 49152 B -> 4 CTAs/SM

typedef unsigned long long ull;

// Blackwell packed dual-FMA (FFMA2 in SASS): 2x fp32 FMA per issue.
__device__ __forceinline__ ull ffma2(ull a, ull b, ull c) {
    ull d;
    asm("fma.rn.f32x2 %0, %1, %2, %3;" : "=l"(d) : "l"(a), "l"(b), "l"(c));
    return d;
}

// Accurate cheap tanh: exp form + Taylor branch near 0. Error ~1e-6.
__device__ __forceinline__ float fast_tanh(float x) {
    float xc = fminf(fmaxf(x, -15.0f), 15.0f);
    float t  = __expf(2.0f * xc);
    float r  = __fdividef(t - 1.0f, t + 1.0f);
    float x2 = x * x;
    float p  = x * (1.0f + x2 * (-0.33333334f + 0.13333334f * x2));
    return (fabsf(x) < 0.05f) ? p : r;
}

__global__ __launch_bounds__(NTHREADS, 4)
void dwconv1d_tanh_hiocc_kernel(const float* __restrict__ x,
                                const float* __restrict__ w,     // [K][CC]
                                const float* __restrict__ bias,  // [CC]
                                float* __restrict__ out) {
    extern __shared__ float sm[];
    float* sx = sm;                  // [ROWS][CH]
    float* sw = sm + SMEM_X_F;       // [KK][CH]

    const int tid  = threadIdx.x;
    const int blk  = blockIdx.x;
    const int half = blk & 1;                 // channel half
    const int tile = (blk >> 1) & 511;        // LL/TL = 512 tiles
    const int b    = blk >> 10;
    const int t0   = tile * TL;

    // ---- stage weights half: 64 rows x 16 float4 ----
    {
        const float4* wsrc = (const float4*)w;    // row stride CC/4 = 32
        float4*       wdst = (float4*)sw;
        #pragma unroll
        for (int n = 0; n < (SMEM_W_F / 4) / NTHREADS; n++) {   // 4 iters
            int idx = tid + n * NTHREADS;         // 0..1023
            int k   = idx >> 4;
            int col = idx & 15;
            wdst[idx] = wsrc[k * 32 + half * 16 + col];
        }
    }

    // ---- stage x half-rows [t0-31, t0+97), zero-padded ----
    {
        const int base = t0 - PADL;
        const float4* xsrc = (const float4*)(x + (size_t)b * LL * CC); // row stride 32 f4
        float4*       xdst = (float4*)sx;                              // row stride 16 f4
        #pragma unroll
        for (int n = 0; n < (SMEM_X_F / 4) / NTHREADS; n++) {   // 8 iters
            int idx = tid + n * NTHREADS;         // 0..2047
            int r   = idx >> 4;
            int col = idx & 15;
            int g   = base + r;
            float4 v = make_float4(0.f, 0.f, 0.f, 0.f);
            if ((unsigned)g < (unsigned)LL)
                v = xsrc[(size_t)g * 32 + half * 16 + col];
            xdst[idx] = v;
        }
    }
    __syncthreads();

    const int c2    = tid & (CP - 1);   // channel pair within half
    const int ts    = tid >> 5;         // 0..7 (warp-uniform)
    const int jbase = ts * TT;

    // Immediate-offset LDS bases (row stride CP ull = 256 B).
    const ull* sx2 = ((const ull*)sx) + (size_t)jbase * CP + c2;
    const ull* sw2 = ((const ull*)sw) + c2;

    ull acc[TT];
    #pragma unroll
    for (int j = 0; j < TT; j++) acc[j] = 0ull;

    // Rolling 8-row register window: xw[(k+j)&7] = shared row (jbase+k+j).
    ull xw[TT];
    #pragma unroll
    for (int q = 0; q < TT; q++) xw[q] = sx2[q * CP];

    ull wk = sw2[0];
    #pragma unroll
    for (int k = 0; k < KK; k++) {
        ull wnext = sw2[((k + 1) & (KK - 1)) * CP];
        ull xnew  = sx2[(k + TT) * CP];      // row jbase+k+8 <= 127: in bounds

        #pragma unroll
        for (int j = 0; j < TT; j++)
            acc[j] = ffma2(xw[(k + j) & (TT - 1)], wk, acc[j]);

        xw[k & (TT - 1)] = xnew;
        wk = wnext;
    }

    // ---- bias + tanh + store (8B/lane, coalesced within half) ----
    const float2 bv = ((const float2*)bias)[half * CP + c2];
    float2* outp = (float2*)out;          // row stride CC/2 = 64 float2
    const size_t ob = ((size_t)b * LL + t0 + jbase) * 64 + half * CP + c2;
    #pragma unroll
    for (int j = 0; j < TT; j++) {
        float2 a = *(float2*)&acc[j];
        float y0 = fast_tanh(a.x + bv.x);
        float y1 = fast_tanh(a.y + bv.y);
        outp[ob + (size_t)j * 64] = make_float2(y0, y1);
    }
}

extern "C" void kernel_launch(void* const* d_in, const int* in_sizes, int n_in,
                              void* d_out, int out_size) {
    const float* x    = (const float*)d_in[0];
    const float* w    = (const float*)d_in[1];
    const float* bias = (const float*)d_in[2];
    float*       out  = (float*)d_out;

    cudaFuncSetAttribute(dwconv1d_tanh_hiocc_kernel,
                         cudaFuncAttributeMaxDynamicSharedMemorySize, SMEM_BYTES);

    // grid: b (32) x tile (512) x half (2); halves adjacent for L2 halo reuse
    dwconv1d_tanh_hiocc_kernel<<<BB * (LL / TL) * 2, NTHREADS, SMEM_BYTES>>>(x, w, bias, out);
}